// round 16
// baseline (speedup 1.0000x reference)
#include <cuda_runtime.h>
#include <cstdint>

#define TN 2048
#define BN 256
#define DN 40
#define HN 128
#define CN 35
#define TDN (TN * DN)

#define NCTA 64            // 64 CTAs x 4 batch rows, fully independent
#define NTHR 256
#define RB 4               // batch rows per CTA
#define K0 (DN + HN)       // 168  (L0: x ++ h0)
#define K1 (HN + HN)       // 256  (L1: h0 ++ h1)

// ---------------------------------------------------------------------------
// Device scratch: transposed x and gate-packed transposed weights.
__device__ __align__(16) float  g_xT[TDN * BN];        // [t*D+d][b]
__device__ __align__(16) float4 g_wt0[K0 * HN];        // [k][u] {Wi,Wf,Wg,Wo}
__device__ __align__(16) float4 g_wt1[K1 * HN];        // [k][u] {Wi,Wf,Wg,Wo}

// ---------------------------------------------------------------------------
union F2U { float2 f; unsigned long long u; };
__device__ __forceinline__ void ffma2(float2& acc, float2 a, float2 b) {
    F2U ua, ub, uc;
    ua.f = a; ub.f = b; uc.f = acc;
    asm("fma.rn.f32x2 %0, %1, %2, %0;" : "+l"(uc.u) : "l"(ua.u), "l"(ub.u));
    acc = uc.f;
}
__device__ __forceinline__ float sigf(float x)  { return 1.0f / (1.0f + __expf(-x)); }
__device__ __forceinline__ float tanhx(float x) {
    x = fminf(fmaxf(x, -15.f), 15.f);
    float e = __expf(2.f * x);
    return (e - 1.f) / (e + 1.f);
}

struct LstmArgs {
    const float *x;
    const int   *length;
    const float *Wih0, *Whh0, *bih0, *bhh0;
    const float *Wih1, *Whh1, *bih1, *bhh1;
    const float *lng, *lnb, *fcw, *fcb;
    float       *out;
};

// ---------------------------------------------------------------------------
// Transpose x [B][T*D] -> g_xT [T*D][B]  (one-time per launch).
__global__ void transpose_kernel(const float* __restrict__ x) {
    __shared__ float tile[32][33];
    int tdBase = blockIdx.x * 32;
    int bBase  = blockIdx.y * 32;
    int tx = threadIdx.x, ty = threadIdx.y;   // 32 x 8
#pragma unroll
    for (int j = 0; j < 4; j++)
        tile[ty + j * 8][tx] = x[(size_t)(bBase + ty + j * 8) * TDN + tdBase + tx];
    __syncthreads();
#pragma unroll
    for (int j = 0; j < 4; j++)
        g_xT[(size_t)(tdBase + ty + j * 8) * BN + bBase + tx] = tile[tx][ty + j * 8];
}

// Gate-pack + transpose weights into [k][u] float4 {Wi,Wf,Wg,Wo}.
__global__ void wtrans_kernel(const float* __restrict__ Wih0,
                              const float* __restrict__ Whh0,
                              const float* __restrict__ Wih1,
                              const float* __restrict__ Whh1) {
    int idx = blockIdx.x * blockDim.x + threadIdx.x;
    int total0 = K0 * HN;
    int total1 = K1 * HN;
    if (idx < total0) {
        int k = idx / HN, u = idx - k * HN;
        float4 w;
        if (k < DN) {
            w.x = Wih0[(0 * HN + u) * DN + k];
            w.y = Wih0[(1 * HN + u) * DN + k];
            w.z = Wih0[(2 * HN + u) * DN + k];
            w.w = Wih0[(3 * HN + u) * DN + k];
        } else {
            int kk = k - DN;
            w.x = Whh0[(0 * HN + u) * HN + kk];
            w.y = Whh0[(1 * HN + u) * HN + kk];
            w.z = Whh0[(2 * HN + u) * HN + kk];
            w.w = Whh0[(3 * HN + u) * HN + kk];
        }
        g_wt0[idx] = w;
    } else if (idx < total0 + total1) {
        int j = idx - total0;
        int k = j / HN, u = j - k * HN;
        float4 w;
        if (k < HN) {
            w.x = Wih1[(0 * HN + u) * HN + k];
            w.y = Wih1[(1 * HN + u) * HN + k];
            w.z = Wih1[(2 * HN + u) * HN + k];
            w.w = Wih1[(3 * HN + u) * HN + k];
        } else {
            int kk = k - HN;
            w.x = Whh1[(0 * HN + u) * HN + kk];
            w.y = Whh1[(1 * HN + u) * HN + kk];
            w.z = Whh1[(2 * HN + u) * HN + kk];
            w.w = Whh1[(3 * HN + u) * HN + kk];
        }
        g_wt1[j] = w;
    }
}

// ---------------------------------------------------------------------------
// Main kernel: one CTA = 4 batch rows, full 2-layer LSTM, zero inter-CTA sync.
// 256 threads: u = unit 0..127 (warps 0-3 / 4-7 mirror), kh = tid>>7 k-half.
// Inputs staged dup'd in SMEM: in0 = [x(t) | h0(t-1)], in1 = [h0(t) | h1(t-1)].
struct SmemD {
    float2 in0[K0][RB];    // 5.25 KB
    float2 in1[K1][RB];    // 8 KB
    float2 red[HN][8];     // k-split partials, 8 KB
    float  hv[HN + 16];    // head scratch
    float  rr[4];
};

// MAC over [kb,ke) of a dup'd input tile against streamed weights.
__device__ __forceinline__ void mac_stream(
    float2 accIF[RB], float2 accGO[RB],
    const float4* __restrict__ wt,   // + kb*HN + u already applied
    const float2 (*inp)[RB],         // + kb already applied
    int n)
{
#pragma unroll 4
    for (int j = 0; j < n; j++) {
        float4 w  = __ldcg(wt + (size_t)j * HN);
        float4 da = *(const float4*)&inp[j][0];   // {v0,v0,v1,v1}
        float4 db = *(const float4*)&inp[j][2];   // {v2,v2,v3,v3}
        float2 wif = make_float2(w.x, w.y);
        float2 wgo = make_float2(w.z, w.w);
        ffma2(accIF[0], wif, make_float2(da.x, da.y));
        ffma2(accGO[0], wgo, make_float2(da.x, da.y));
        ffma2(accIF[1], wif, make_float2(da.z, da.w));
        ffma2(accGO[1], wgo, make_float2(da.z, da.w));
        ffma2(accIF[2], wif, make_float2(db.x, db.y));
        ffma2(accGO[2], wgo, make_float2(db.x, db.y));
        ffma2(accIF[3], wif, make_float2(db.z, db.w));
        ffma2(accGO[3], wgo, make_float2(db.z, db.w));
    }
}

__global__ void __launch_bounds__(NTHR, 1) lstm_bs(LstmArgs a)
{
    __shared__ SmemD sm;
    const int tid   = threadIdx.x;
    const int bid   = blockIdx.x;
    const int bbase = bid * RB;
    const int kh    = tid >> 7;                       // k-half
    const int u     = ((tid >> 5) & 3) * 32 + (tid & 31);  // unit 0..127

    // ---- init: zero input tiles ----
    {
        float2* z0 = &sm.in0[0][0];
        for (int i = tid; i < K0 * RB; i += NTHR) z0[i] = make_float2(0.f, 0.f);
        float2* z1 = &sm.in1[0][0];
        for (int i = tid; i < K1 * RB; i += NTHR) z1[i] = make_float2(0.f, 0.f);
    }

    // bias registers (used by kh=0 accumulator init)
    const float2 b0if = make_float2(a.bih0[0 * HN + u] + a.bhh0[0 * HN + u],
                                    a.bih0[1 * HN + u] + a.bhh0[1 * HN + u]);
    const float2 b0go = make_float2(a.bih0[2 * HN + u] + a.bhh0[2 * HN + u],
                                    a.bih0[3 * HN + u] + a.bhh0[3 * HN + u]);
    const float2 b1if = make_float2(a.bih1[0 * HN + u] + a.bhh1[0 * HN + u],
                                    a.bih1[1 * HN + u] + a.bhh1[1 * HN + u]);
    const float2 b1go = make_float2(a.bih1[2 * HN + u] + a.bhh1[2 * HN + u],
                                    a.bih1[3 * HN + u] + a.bhh1[3 * HN + u]);

    int len[RB];
#pragma unroll
    for (int j = 0; j < RB; j++) len[j] = a.length[bbase + j];

    // per-unit recurrent state for this thread's unit (kh=0 threads own it)
    float c0[RB], h0s[RB], c1[RB], h1s[RB];
#pragma unroll
    for (int j = 0; j < RB; j++) { c0[j] = 0.f; h0s[j] = 0.f; c1[j] = 0.f; h1s[j] = 0.f; }

    // x prefetch: threads 0..39 hold the next x row-slice (4 batch) in regs
    const bool xst = tid < DN;
    float4 xr = make_float4(0.f, 0.f, 0.f, 0.f);
    if (xst)
        xr = __ldcg((const float4*)(g_xT + (size_t)tid * BN + bbase));

    // MAC ranges (k-split halves)
    const int kb0 = kh * (K0 / 2);            // 0 / 84
    const int kb1 = kh * (K1 / 2);            // 0 / 128
    const float4* wt0p = g_wt0 + (size_t)kb0 * HN + u;
    const float4* wt1p = g_wt1 + (size_t)kb1 * HN + u;

    __syncthreads();

    // ---- step loop: entirely CTA-local ----
#pragma unroll 1
    for (int t = 0; t < TN; t++) {
        // write x(t) dup tile
        if (xst) {
            sm.in0[tid][0] = make_float2(xr.x, xr.x);
            sm.in0[tid][1] = make_float2(xr.y, xr.y);
            sm.in0[tid][2] = make_float2(xr.z, xr.z);
            sm.in0[tid][3] = make_float2(xr.w, xr.w);
        }
        __syncthreads();

        // ===== layer 0 =====
        float2 accIF[RB], accGO[RB];
        if (kh == 0) {
#pragma unroll
            for (int j = 0; j < RB; j++) { accIF[j] = b0if; accGO[j] = b0go; }
        } else {
#pragma unroll
            for (int j = 0; j < RB; j++) {
                accIF[j] = make_float2(0.f, 0.f);
                accGO[j] = make_float2(0.f, 0.f);
            }
        }
        mac_stream(accIF, accGO, wt0p, &sm.in0[kb0], K0 / 2);

        // prefetch next x while MAC results settle
        if (xst && t + 1 < TN)
            xr = __ldcg((const float4*)(g_xT + ((size_t)(t + 1) * DN + tid) * BN + bbase));

        if (kh == 1) {
#pragma unroll
            for (int j = 0; j < RB; j++) {
                sm.red[u][j]     = accIF[j];
                sm.red[u][j + 4] = accGO[j];
            }
        }
        __syncthreads();
        if (kh == 0) {
#pragma unroll
            for (int j = 0; j < RB; j++) {
                float2 pIF = sm.red[u][j], pGO = sm.red[u][j + 4];
                accIF[j].x += pIF.x; accIF[j].y += pIF.y;
                accGO[j].x += pGO.x; accGO[j].y += pGO.y;
            }
            float hd[RB];
#pragma unroll
            for (int j = 0; j < RB; j++) {
                float i_ = sigf(accIF[j].x), f_ = sigf(accIF[j].y);
                float g_ = tanhx(accGO[j].x), o_ = sigf(accGO[j].y);
                float cn = f_ * c0[j] + i_ * g_;
                float hn = o_ * tanhx(cn);
                if (t < len[j]) { c0[j] = cn; h0s[j] = hn; }
                hd[j] = h0s[j];
            }
            // h0(t) feeds L0 part-2 (next step) and L1 part-1 (this step)
            float4 p0 = make_float4(hd[0], hd[0], hd[1], hd[1]);
            float4 p1 = make_float4(hd[2], hd[2], hd[3], hd[3]);
            *(float4*)&sm.in0[DN + u][0] = p0;
            *(float4*)&sm.in0[DN + u][2] = p1;
            *(float4*)&sm.in1[u][0] = p0;
            *(float4*)&sm.in1[u][2] = p1;
        }
        __syncthreads();

        // ===== layer 1 =====
        if (kh == 0) {
#pragma unroll
            for (int j = 0; j < RB; j++) { accIF[j] = b1if; accGO[j] = b1go; }
        } else {
#pragma unroll
            for (int j = 0; j < RB; j++) {
                accIF[j] = make_float2(0.f, 0.f);
                accGO[j] = make_float2(0.f, 0.f);
            }
        }
        mac_stream(accIF, accGO, wt1p, &sm.in1[kb1], K1 / 2);

        if (kh == 1) {
#pragma unroll
            for (int j = 0; j < RB; j++) {
                sm.red[u][j]     = accIF[j];
                sm.red[u][j + 4] = accGO[j];
            }
        }
        __syncthreads();
        if (kh == 0) {
#pragma unroll
            for (int j = 0; j < RB; j++) {
                float2 pIF = sm.red[u][j], pGO = sm.red[u][j + 4];
                accIF[j].x += pIF.x; accIF[j].y += pIF.y;
                accGO[j].x += pGO.x; accGO[j].y += pGO.y;
            }
            float hd[RB];
#pragma unroll
            for (int j = 0; j < RB; j++) {
                float i_ = sigf(accIF[j].x), f_ = sigf(accIF[j].y);
                float g_ = tanhx(accGO[j].x), o_ = sigf(accGO[j].y);
                float cn = f_ * c1[j] + i_ * g_;
                float hn = o_ * tanhx(cn);
                if (t < len[j]) { c1[j] = cn; h1s[j] = hn; }
                hd[j] = h1s[j];
            }
            *(float4*)&sm.in1[HN + u][0] = make_float4(hd[0], hd[0], hd[1], hd[1]);
            *(float4*)&sm.in1[HN + u][2] = make_float4(hd[2], hd[2], hd[3], hd[3]);
        }
        __syncthreads();
    }

    // ---- head: LN + FC for this CTA's 4 batch rows (all data local) ----
    for (int row = 0; row < RB; row++) {
        float v = (tid < HN) ? sm.in1[HN + tid][row].x : 0.f;

        float s = v;
#pragma unroll
        for (int o = 16; o; o >>= 1) s += __shfl_xor_sync(0xffffffffu, s, o);
        if ((tid & 31) == 0 && tid < HN) sm.rr[tid >> 5] = s;
        __syncthreads();
        float mu = (sm.rr[0] + sm.rr[1] + sm.rr[2] + sm.rr[3]) * (1.0f / HN);

        float d = (tid < HN) ? (v - mu) : 0.f;
        float q = d * d;
#pragma unroll
        for (int o = 16; o; o >>= 1) q += __shfl_xor_sync(0xffffffffu, q, o);
        __syncthreads();
        if ((tid & 31) == 0 && tid < HN) sm.rr[tid >> 5] = q;
        __syncthreads();
        float var = (sm.rr[0] + sm.rr[1] + sm.rr[2] + sm.rr[3]) * (1.0f / HN);

        if (tid < HN)
            sm.hv[tid] = d * rsqrtf(var + 1e-5f) * a.lng[tid] + a.lnb[tid];
        __syncthreads();

        if (tid < CN) {
            float acc = a.fcb[tid];
#pragma unroll 4
            for (int k = 0; k < HN; k++)
                acc = fmaf(sm.hv[k], a.fcw[tid * HN + k], acc);
            a.out[(bbase + row) * CN + tid] = acc;
        }
        __syncthreads();
    }
}

// ---------------------------------------------------------------------------
extern "C" void kernel_launch(void* const* d_in, const int* in_sizes, int n_in,
                              void* d_out, int out_size)
{
    LstmArgs a;
    a.x      = (const float*)d_in[0];
    a.length = (const int*)  d_in[1];
    a.Wih0 = (const float*)d_in[2];
    a.Whh0 = (const float*)d_in[3];
    a.bih0 = (const float*)d_in[4];
    a.bhh0 = (const float*)d_in[5];
    a.Wih1 = (const float*)d_in[6];
    a.Whh1 = (const float*)d_in[7];
    a.bih1 = (const float*)d_in[8];
    a.bhh1 = (const float*)d_in[9];
    a.lng  = (const float*)d_in[10];
    a.lnb  = (const float*)d_in[11];
    a.fcw  = (const float*)d_in[12];
    a.fcb  = (const float*)d_in[13];
    a.out  = (float*)d_out;

    // One-time (per launch) data-layout passes.
    dim3 tgrid(TDN / 32, BN / 32);
    dim3 tblk(32, 8);
    transpose_kernel<<<tgrid, tblk>>>(a.x);

    int wtot = K0 * HN + K1 * HN;
    wtrans_kernel<<<(wtot + 255) / 256, 256>>>(a.Wih0, a.Whh0, a.Wih1, a.Whh1);

    // Main: 64 fully independent CTAs.
    lstm_bs<<<NCTA, NTHR>>>(a);
}

// round 17
// speedup vs baseline: 2.2070x; 2.2070x over previous
#include <cuda_runtime.h>
#include <cstdint>

#define TN 2048
#define BN 256
#define DN 40
#define HN 128
#define CN 35
#define TDN (TN * DN)
#define NCTA 128
#define NTHR 256

// ---------------------------------------------------------------------------
// Persistent device scratch.
__device__ __align__(16) float g_xT[TDN * BN];     // x transposed: [t*D + d][b]
__device__ __align__(16) float g_h0[2][HN * BN];   // layer0 h double buffer, [k][b]
__device__ __align__(16) float g_h1[2][HN * BN];   // layer1 h double buffer, [k][b]

struct alignas(128) BarSlot { unsigned v; };
__device__ BarSlot g_cnt;
__device__ volatile BarSlot g_phz;                 // monotonic phase
__device__ __align__(128) unsigned g_flag[4][32];  // [group][ublock] step counters

// ---------------------------------------------------------------------------
union F2U { float2 f; unsigned long long u; };
__device__ __forceinline__ void ffma2(float2& acc, float2 a, float2 b) {
    F2U ua, ub, uc;
    ua.f = a; ub.f = b; uc.f = acc;
    asm("fma.rn.f32x2 %0, %1, %2, %0;" : "+l"(uc.u) : "l"(ua.u), "l"(ub.u));
    acc = uc.f;
}
__device__ __forceinline__ float sigf(float x)  { return 1.0f / (1.0f + __expf(-x)); }
__device__ __forceinline__ float tanhx(float x) {
    x = fminf(fmaxf(x, -15.f), 15.f);
    float e = __expf(2.f * x);
    return (e - 1.f) / (e + 1.f);
}
__device__ __forceinline__ unsigned ldacq(const unsigned* p) {
    unsigned v;
    asm volatile("ld.acquire.gpu.global.u32 %0, [%1];" : "=r"(v) : "l"(p) : "memory");
    return v;
}
__device__ __forceinline__ void strel(unsigned* p, unsigned v) {
    asm volatile("st.release.gpu.global.u32 [%0], %1;" :: "l"(p), "r"(v) : "memory");
}

__device__ __forceinline__ void gbar_full() {
    __syncthreads();
    if (threadIdx.x == 0) {
        unsigned ph = g_phz.v;
        __threadfence();
        if (atomicAdd(&g_cnt.v, 1u) == NCTA - 1u) {
            g_cnt.v = 0u;
            __threadfence();
            g_phz.v = ph + 1u;
        } else {
            while (g_phz.v == ph) { }
            __threadfence();
        }
    }
    __syncthreads();
}

// ---------------------------------------------------------------------------
// SMEM (~109 KB dynamic). Weights gate-pair packed: w[u][k][gp] = {w_g0, w_g1}.
struct alignas(16) SmemF {
    float2 wx [4][DN][2];
    float2 wh0[4][HN][2];
    float2 w1i[4][HN][2];
    float2 w1h[4][HN][2];
    float2 sb[2][4][2];
    float  sx [DN * 64];
    float  sh0[HN * 64];
    float  sh1[HN * 64];
    float2 redA[4][32][4];   // kh0 -> acc of unit lu0+1
    float2 redB[4][32][4];   // kh1 -> acc of unit lu0
};
#define SMEM_BYTES ((int)sizeof(SmemF))

struct LstmArgs {
    const float *x;
    const int   *length;
    const float *Wih0, *Whh0, *bih0, *bhh0;
    const float *Wih1, *Whh1, *bih1, *bhh1;
    const float *lng, *lnb, *fcw, *fcb;
    float       *out;
};

__device__ __forceinline__ void mac_seg(
    float2 acc0[4], float2 acc1[4],
    const float4* __restrict__ w0, const float4* __restrict__ w1,
    const float* __restrict__ sv, int kb, int ke)
{
#pragma unroll 4
    for (int k = kb; k < ke; k++) {
        float2 v  = *(const float2*)(sv + (k << 6));
        float2 d0 = make_float2(v.x, v.x);
        float2 d1 = make_float2(v.y, v.y);
        float4 wa = w0[k];
        ffma2(acc0[0], make_float2(wa.x, wa.y), d0);
        ffma2(acc0[1], make_float2(wa.z, wa.w), d0);
        ffma2(acc0[2], make_float2(wa.x, wa.y), d1);
        ffma2(acc0[3], make_float2(wa.z, wa.w), d1);
        float4 wb = w1[k];
        ffma2(acc1[0], make_float2(wb.x, wb.y), d0);
        ffma2(acc1[1], make_float2(wb.z, wb.w), d0);
        ffma2(acc1[2], make_float2(wb.x, wb.y), d1);
        ffma2(acc1[3], make_float2(wb.z, wb.w), d1);
    }
}

// ---------------------------------------------------------------------------
// Single persistent kernel (R8 skeleton + SMSP rebalance + split epilogue).
__global__ void __launch_bounds__(NTHR, 1) lstm_kernel(LstmArgs a) {
    extern __shared__ char smem_raw[];
    SmemF* sm = (SmemF*)smem_raw;
    const int bid = blockIdx.x;
    const int tid = threadIdx.x;

    const int ub    = bid >> 2;
    const int grp   = bid & 3;
    const int u0    = ub * 4;
    const int bbase = grp * 64;

    // ---- phase 0: transpose x, zero state + flags, pack weights ----
    {
        float (*tile)[33] = (float(*)[33])sm->sh0;
        const int tx = tid & 31, ty = tid >> 5;
        const int ntile = (TDN / 32) * (BN / 32);
        for (int tl = bid; tl < ntile; tl += NCTA) {
            int tdBase = (tl % (TDN / 32)) * 32;
            int bBase  = (tl / (TDN / 32)) * 32;
#pragma unroll
            for (int j = 0; j < 4; j++)
                tile[ty + j * 8][tx] =
                    a.x[(size_t)(bBase + ty + j * 8) * TDN + tdBase + tx];
            __syncthreads();
#pragma unroll
            for (int j = 0; j < 4; j++)
                g_xT[(size_t)(tdBase + ty + j * 8) * BN + bBase + tx] =
                    tile[tx][ty + j * 8];
            __syncthreads();
        }
        for (int i = bid * NTHR + tid; i < HN * BN; i += NCTA * NTHR) {
            g_h0[0][i] = 0.f; g_h0[1][i] = 0.f;
            g_h1[0][i] = 0.f; g_h1[1][i] = 0.f;
        }
        if (bid == 0 && tid < 128)
            *(volatile unsigned*)&g_flag[tid >> 5][tid & 31] = 0u;

        for (int i = tid; i < 4 * DN; i += NTHR) {
            int u = i / DN, k = i - u * DN, r = u0 + u;
            sm->wx[u][k][0] = make_float2(a.Wih0[(0 * HN + r) * DN + k],
                                          a.Wih0[(1 * HN + r) * DN + k]);
            sm->wx[u][k][1] = make_float2(a.Wih0[(2 * HN + r) * DN + k],
                                          a.Wih0[(3 * HN + r) * DN + k]);
        }
        for (int i = tid; i < 4 * HN; i += NTHR) {
            int u = i >> 7, k = i & 127, r = u0 + u;
            sm->wh0[u][k][0] = make_float2(a.Whh0[(0 * HN + r) * HN + k],
                                           a.Whh0[(1 * HN + r) * HN + k]);
            sm->wh0[u][k][1] = make_float2(a.Whh0[(2 * HN + r) * HN + k],
                                           a.Whh0[(3 * HN + r) * HN + k]);
            sm->w1i[u][k][0] = make_float2(a.Wih1[(0 * HN + r) * HN + k],
                                           a.Wih1[(1 * HN + r) * HN + k]);
            sm->w1i[u][k][1] = make_float2(a.Wih1[(2 * HN + r) * HN + k],
                                           a.Wih1[(3 * HN + r) * HN + k]);
            sm->w1h[u][k][0] = make_float2(a.Whh1[(0 * HN + r) * HN + k],
                                           a.Whh1[(1 * HN + r) * HN + k]);
            sm->w1h[u][k][1] = make_float2(a.Whh1[(2 * HN + r) * HN + k],
                                           a.Whh1[(3 * HN + r) * HN + k]);
        }
        if (tid < 16) {
            int s = tid >> 3, u = (tid >> 1) & 3, gp = tid & 1, r = u0 + u;
            const float* bi = s ? a.bih1 : a.bih0;
            const float* bh = s ? a.bhh1 : a.bhh0;
            int g0 = gp * 2, g1 = gp * 2 + 1;
            sm->sb[s][u][gp] = make_float2(bi[g0 * HN + r] + bh[g0 * HN + r],
                                           bi[g1 * HN + r] + bh[g1 * HN + r]);
        }
    }
    gbar_full();

    // ---- phase 1: fused 2-layer step loop ----
    {
        const int wid  = tid >> 5;
        const int lane = tid & 31;
        // Role permutation: every SMSP gets one L0 + one L1 warp AND one
        // kh0 + one kh1 warp (R8 had all kh0 warps on SMSPs 0/2).
        const int s    = wid >> 2;
        const int up   = wid & 1;
        const int kh   = (wid ^ (wid >> 1) ^ (wid >> 2)) & 1;
        const int lu0  = up * 2;
        const int b0   = 2 * lane;
        const int ridx = s * 2 + up;
        const int myu  = u0 + lu0 + kh;     // unit this warp's epilogue owns

        const int len0 = a.length[bbase + b0];
        const int len1 = a.length[bbase + b0 + 1];

        const float4* wp1u0 = s ? (const float4*)&sm->w1i[lu0][0][0]
                                : (const float4*)&sm->wx [lu0][0][0];
        const float4* wp1u1 = s ? (const float4*)&sm->w1i[lu0 + 1][0][0]
                                : (const float4*)&sm->wx [lu0 + 1][0][0];
        const float4* wp2u0 = s ? (const float4*)&sm->w1h[lu0][0][0]
                                : (const float4*)&sm->wh0[lu0][0][0];
        const float4* wp2u1 = s ? (const float4*)&sm->w1h[lu0 + 1][0][0]
                                : (const float4*)&sm->wh0[lu0 + 1][0][0];
        const float* in1base = s ? sm->sh0 : sm->sx;
        const int kb1 = s ? (kh * 64) : (kh * 20);
        const int ke1 = s ? (kh * 64 + 64) : (kh * 20 + 20);
        const int kb2 = kh * 64, ke2 = kb2 + 64;

        // Recurrent state for THIS warp's unit (myu), rows b0 / b0+1.
        float cR0 = 0.f, cR1 = 0.f, hR0 = 0.f, hR1 = 0.f;

#pragma unroll 1
        for (int it = 0; it <= TN; it++) {
            if (it < TN) {
                const float* xsrc = g_xT + (size_t)it * DN * BN + bbase;
                for (int i = tid; i < DN * 16; i += NTHR) {
                    int r = i >> 4, j = (i & 15) << 2;
                    *(float4*)(sm->sx + r * 64 + j) =
                        __ldcg((const float4*)(xsrc + (size_t)r * BN + j));
                }
            }
            // flag wait with backoff (reduces L2 line contention)
            if (tid < 32) {
                unsigned tgt = (unsigned)it;
                if (ldacq(&g_flag[grp][tid]) < tgt)
                    while (ldacq(&g_flag[grp][tid]) < tgt) __nanosleep(32);
            }
            __syncthreads();

            {
                const float* s0 = g_h0[(it + 1) & 1] + bbase;
                const float* s1 = g_h1[it & 1] + bbase;
                for (int i = tid; i < HN * 16; i += NTHR) {
                    int r = i >> 4, j = (i & 15) << 2;
                    *(float4*)(sm->sh0 + r * 64 + j) =
                        __ldcg((const float4*)(s0 + (size_t)r * BN + j));
                    *(float4*)(sm->sh1 + r * 64 + j) =
                        __ldcg((const float4*)(s1 + (size_t)r * BN + j));
                }
            }
            __syncthreads();

            const bool active = s ? (it >= 1) : (it < TN);
            float2 acc0[4], acc1[4];
            if (active) {
                if (kh == 0) {
#pragma unroll
                    for (int j = 0; j < 4; j++) {
                        acc0[j] = sm->sb[s][lu0][j & 1];
                        acc1[j] = sm->sb[s][lu0 + 1][j & 1];
                    }
                } else {
#pragma unroll
                    for (int j = 0; j < 4; j++) {
                        acc0[j] = make_float2(0.f, 0.f);
                        acc1[j] = make_float2(0.f, 0.f);
                    }
                }
                mac_seg(acc0, acc1, wp1u0, wp1u1, in1base + b0, kb1, ke1);
                mac_seg(acc0, acc1, wp2u0, wp2u1,
                        (s ? sm->sh1 : sm->sh0) + b0, kb2, ke2);

                // ship the partner-unit half; keep my unit's half
                if (kh == 0) {
#pragma unroll
                    for (int j = 0; j < 4; j++)
                        sm->redA[ridx][lane][j] = acc1[j];
                } else {
#pragma unroll
                    for (int j = 0; j < 4; j++)
                        sm->redB[ridx][lane][j] = acc0[j];
                }
            }
            __syncthreads();

            if (active) {
                // merge with partner's partial for my unit
                float2 g0, g1, g2, g3;
                if (kh == 0) {
                    float2 p0 = sm->redB[ridx][lane][0];
                    float2 p1 = sm->redB[ridx][lane][1];
                    float2 p2 = sm->redB[ridx][lane][2];
                    float2 p3 = sm->redB[ridx][lane][3];
                    g0 = make_float2(acc0[0].x + p0.x, acc0[0].y + p0.y);
                    g1 = make_float2(acc0[1].x + p1.x, acc0[1].y + p1.y);
                    g2 = make_float2(acc0[2].x + p2.x, acc0[2].y + p2.y);
                    g3 = make_float2(acc0[3].x + p3.x, acc0[3].y + p3.y);
                } else {
                    float2 p0 = sm->redA[ridx][lane][0];
                    float2 p1 = sm->redA[ridx][lane][1];
                    float2 p2 = sm->redA[ridx][lane][2];
                    float2 p3 = sm->redA[ridx][lane][3];
                    g0 = make_float2(acc1[0].x + p0.x, acc1[0].y + p0.y);
                    g1 = make_float2(acc1[1].x + p1.x, acc1[1].y + p1.y);
                    g2 = make_float2(acc1[2].x + p2.x, acc1[2].y + p2.y);
                    g3 = make_float2(acc1[3].x + p3.x, acc1[3].y + p3.y);
                }
                const int t = s ? (it - 1) : it;
                {   // row b0
                    float i_ = sigf(g0.x), f_ = sigf(g0.y);
                    float g_ = tanhx(g1.x), o_ = sigf(g1.y);
                    float cn = f_ * cR0 + i_ * g_;
                    float hn = o_ * tanhx(cn);
                    if (t < len0) { cR0 = cn; hR0 = hn; }
                }
                {   // row b0+1
                    float i_ = sigf(g2.x), f_ = sigf(g2.y);
                    float g_ = tanhx(g3.x), o_ = sigf(g3.y);
                    float cn = f_ * cR1 + i_ * g_;
                    float hn = o_ * tanhx(cn);
                    if (t < len1) { cR1 = cn; hR1 = hn; }
                }
                float* hout = s ? g_h1[(it + 1) & 1] : g_h0[it & 1];
                __stcg((float2*)&hout[(size_t)myu * BN + bbase + b0],
                       make_float2(hR0, hR1));
            }
            __syncthreads();
            if (tid == 0) {
                __threadfence();
                strel(&g_flag[grp][ub], (unsigned)(it + 1));
            }
        }
    }
    gbar_full();

    // ---- phase 2: LN + FC head (2 batch rows per CTA) ----
    {
        float* hv  = sm->sx;
        float* red = sm->sx + 160;
        const int brow = bid * 2;

        for (int rep = 0; rep < 2; rep++) {
            int b = brow + rep;
            float v = (tid < HN)
                ? __ldcg(&g_h1[(TN - 1) & 1][(size_t)tid * BN + b]) : 0.f;

            float sum = v;
#pragma unroll
            for (int o = 16; o; o >>= 1) sum += __shfl_xor_sync(0xffffffffu, sum, o);
            if ((tid & 31) == 0 && tid < HN) red[tid >> 5] = sum;
            __syncthreads();
            float mu = (red[0] + red[1] + red[2] + red[3]) * (1.0f / HN);

            float d = (tid < HN) ? (v - mu) : 0.f;
            float q = d * d;
#pragma unroll
            for (int o = 16; o; o >>= 1) q += __shfl_xor_sync(0xffffffffu, q, o);
            __syncthreads();
            if ((tid & 31) == 0 && tid < HN) red[tid >> 5] = q;
            __syncthreads();
            float var = (red[0] + red[1] + red[2] + red[3]) * (1.0f / HN);

            if (tid < HN)
                hv[tid] = d * rsqrtf(var + 1e-5f) * a.lng[tid] + a.lnb[tid];
            __syncthreads();

            if (tid < CN) {
                float acc = a.fcb[tid];
#pragma unroll 4
                for (int h = 0; h < HN; h++)
                    acc = fmaf(hv[h], a.fcw[tid * HN + h], acc);
                a.out[b * CN + tid] = acc;
            }
            __syncthreads();
        }
    }
}

// ---------------------------------------------------------------------------
extern "C" void kernel_launch(void* const* d_in, const int* in_sizes, int n_in,
                              void* d_out, int out_size)
{
    LstmArgs a;
    a.x      = (const float*)d_in[0];
    a.length = (const int*)  d_in[1];
    a.Wih0 = (const float*)d_in[2];
    a.Whh0 = (const float*)d_in[3];
    a.bih0 = (const float*)d_in[4];
    a.bhh0 = (const float*)d_in[5];
    a.Wih1 = (const float*)d_in[6];
    a.Whh1 = (const float*)d_in[7];
    a.bih1 = (const float*)d_in[8];
    a.bhh1 = (const float*)d_in[9];
    a.lng  = (const float*)d_in[10];
    a.lnb  = (const float*)d_in[11];
    a.fcw  = (const float*)d_in[12];
    a.fcb  = (const float*)d_in[13];
    a.out  = (float*)d_out;

    static bool attr_done = false;
    if (!attr_done) {
        cudaFuncSetAttribute(lstm_kernel,
                             cudaFuncAttributeMaxDynamicSharedMemorySize,
                             SMEM_BYTES);
        attr_done = true;
    }

    lstm_kernel<<<NCTA, NTHR, SMEM_BYTES>>>(a);
}